// round 4
// baseline (speedup 1.0000x reference)
#include <cuda_runtime.h>

// Problem constants (fixed by setup_inputs)
#define TWO_E   1600000
#define NE      800000
#define NN      50000
#define NBLK    (NN + 2*NE)          // 1,650,000 blocks total
#define NENT    (NBLK*16)            // 26,400,000 COO entries
#define SCAN_B  1024
#define NSB     ((NN + SCAN_B - 1)/SCAN_B)   // 49
#define MAXL    128                  // per-node local sort capacity

// Scratch (static device globals; no allocation)
__device__ float                  g_diag[NN*16];     // maps_diag accumulator
__device__ unsigned int           g_cnt[NN];         // edge-blocks per node
__device__ unsigned int           g_off[NN+1];       // exclusive scan of (cnt+1)
__device__ unsigned int           g_cur[NN];         // fill cursors
__device__ unsigned long long     g_key[NBLK];       // (t<<22)|(cat<<20)|e
__device__ int                    g_nodeOf[NBLK];    // slot -> node
__device__ unsigned int           g_run[NBLK];       // (run_len<<16)|idx_in_run
__device__ unsigned int           g_partial[NSB];    // scan partials

__global__ void k_zero() {
    int i = blockIdx.x * blockDim.x + threadIdx.x;
    if (i < NN*16) g_diag[i] = 0.0f;
    if (i < NN)    g_cnt[i]  = 0u;
}

// Per-edge M^T M scatter-add into g_diag (all 2E rows of edge_index[0]),
// plus degree counting for the first E edges.
__global__ void k_diag_count(const float* __restrict__ maps,
                             const int*   __restrict__ ei) {
    int j = blockIdx.x * blockDim.x + threadIdx.x;
    if (j >= TWO_E) return;
    const float4* M = reinterpret_cast<const float4*>(maps + (size_t)j * 16);
    float4 r0 = M[0], r1 = M[1], r2 = M[2], r3 = M[3];
    float m[4][4] = {
        {r0.x, r0.y, r0.z, r0.w},
        {r1.x, r1.y, r1.z, r1.w},
        {r2.x, r2.y, r2.z, r2.w},
        {r3.x, r3.y, r3.z, r3.w}
    };
    int node = ei[j];                       // edge_index[0][j]
    float* dst = g_diag + (size_t)node * 16;
#pragma unroll
    for (int a = 0; a < 4; a++) {
#pragma unroll
        for (int b = 0; b < 4; b++) {
            float c = m[0][a]*m[0][b] + m[1][a]*m[1][b]
                    + m[2][a]*m[2][b] + m[3][a]*m[3][b];
            atomicAdd(dst + a*4 + b, c);
        }
    }
    if (j < NE) {
        atomicAdd(&g_cnt[node], 1u);               // row[e]  (cat1 block)
        atomicAdd(&g_cnt[ei[TWO_E + j]], 1u);      // col[e]  (cat2 block)
    }
}

// 3-launch exclusive scan over (cnt[i] + 1)
__global__ void k_scan1() {
    __shared__ unsigned sh[SCAN_B];
    unsigned i = blockIdx.x * SCAN_B + threadIdx.x;
    unsigned v = (i < NN) ? (g_cnt[i] + 1u) : 0u;
    sh[threadIdx.x] = v;
    __syncthreads();
    for (int d = 1; d < SCAN_B; d <<= 1) {
        unsigned t = (threadIdx.x >= (unsigned)d) ? sh[threadIdx.x - d] : 0u;
        __syncthreads();
        sh[threadIdx.x] += t;
        __syncthreads();
    }
    if (i < NN) g_off[i] = sh[threadIdx.x] - v;     // exclusive within block
    if (threadIdx.x == SCAN_B - 1) g_partial[blockIdx.x] = sh[SCAN_B - 1];
}

__global__ void k_scan2() {
    unsigned run = 0;
    for (int b = 0; b < NSB; b++) {
        unsigned t = g_partial[b];
        g_partial[b] = run;
        run += t;
    }
    g_off[NN] = run;    // == NBLK
}

// Finish scan; also seed diag block key + cursor per node.
__global__ void k_scan3() {
    unsigned i = blockIdx.x * blockDim.x + threadIdx.x;
    if (i >= NN) return;
    unsigned o = g_off[i] + g_partial[i >> 10];
    g_off[i] = o;
    g_key[o]    = ((unsigned long long)i) << 22;    // cat=0, e=0
    g_nodeOf[o] = (int)i;
    g_cur[i]    = o + 1u;
}

// Fill edge blocks: cat1 under row[e] targeting col[e]; cat2 under col[e] targeting row[e].
__global__ void k_fill(const int* __restrict__ ei) {
    int e = blockIdx.x * blockDim.x + threadIdx.x;
    if (e >= NE) return;
    int r = ei[e];
    int c = ei[TWO_E + e];
    unsigned s1 = atomicAdd(&g_cur[r], 1u);
    g_key[s1]    = ((unsigned long long)(unsigned)c << 22) | (1ull << 20) | (unsigned)e;
    g_nodeOf[s1] = r;
    unsigned s2 = atomicAdd(&g_cur[c], 1u);
    g_key[s2]    = ((unsigned long long)(unsigned)r << 22) | (2ull << 20) | (unsigned)e;
    g_nodeOf[s2] = c;
}

// Per-node insertion sort of block keys (keys unique within a node), then
// compute runs of equal target t and store (run_len, idx_in_run) per slot.
__global__ void k_sort() {
    int node = blockIdx.x * blockDim.x + threadIdx.x;
    if (node >= NN) return;
    unsigned off = g_off[node];
    int cnt = (int)(g_off[node + 1] - off);
    if (cnt <= 0) return;

    if (cnt > 1) {
        if (cnt <= MAXL) {
            unsigned long long buf[MAXL];
            for (int i = 0; i < cnt; i++) buf[i] = g_key[off + i];
            for (int i = 1; i < cnt; i++) {
                unsigned long long x = buf[i];
                int j = i - 1;
                while (j >= 0 && buf[j] > x) { buf[j + 1] = buf[j]; j--; }
                buf[j + 1] = x;
            }
            for (int i = 0; i < cnt; i++) g_key[off + i] = buf[i];
            // run detection over local buffer
            int i = 0;
            while (i < cnt) {
                unsigned t = (unsigned)(buf[i] >> 22);
                int j = i + 1;
                while (j < cnt && (unsigned)(buf[j] >> 22) == t) j++;
                unsigned m = (unsigned)(j - i);
                for (int q = i; q < j; q++)
                    g_run[off + q] = (m << 16) | (unsigned)(q - i);
                i = j;
            }
        } else {
            // safety fallback (degree > 128 never happens for this dataset)
            for (int i = 1; i < cnt; i++) {
                unsigned long long x = g_key[off + i];
                int j = i - 1;
                while (j >= 0 && g_key[off + j] > x) { g_key[off + j + 1] = g_key[off + j]; j--; }
                g_key[off + j + 1] = x;
            }
            int i = 0;
            while (i < cnt) {
                unsigned t = (unsigned)(g_key[off + i] >> 22);
                int j = i + 1;
                while (j < cnt && (unsigned)(g_key[off + j] >> 22) == t) j++;
                unsigned m = (unsigned)(j - i);
                for (int q = i; q < j; q++)
                    g_run[off + q] = (m << 16) | (unsigned)(q - i);
                i = j;
            }
        }
    } else {
        g_run[off] = (1u << 16);
    }
}

// Emit: one thread per (block slot, a). Within a (node, a) output row the
// entry order is (t, b, cat, e): blocks with distinct t emit 4 contiguous
// entries; runs of m>1 blocks sharing t emit b-interleaved (stride m).
__global__ void k_emit(const float* __restrict__ maps,
                       float* __restrict__ out) {
    unsigned tid = blockIdx.x * blockDim.x + threadIdx.x;
    if (tid >= (unsigned)NBLK * 4u) return;
    unsigned s = tid >> 2;
    int a = (int)(tid & 3u);

    int node = g_nodeOf[s];
    unsigned off = g_off[node];
    unsigned cnt = g_off[node + 1] - off;
    unsigned k   = s - off;

    unsigned long long key = g_key[s];
    unsigned t   = (unsigned)(key >> 22);
    int      cat = (int)((key >> 20) & 3ull);
    unsigned e   = (unsigned)(key & 0xFFFFFull);

    float4 v;
    if (cat == 0) {
        v = *reinterpret_cast<const float4*>(g_diag + (size_t)node * 16 + a * 4);
    } else {
        const float* L = maps + (size_t)e * 16;
        const float* R = maps + (size_t)(NE + e) * 16;
        // cat1: v[b] = -sum_r L[r][a] * R[r][b]   (triu[a][b])
        // cat2: v[b] = -sum_r R[r][a] * L[r][b]   (triu[b][a])
        const float* sel = (cat == 1) ? L : R;
        const float* mat = (cat == 1) ? R : L;
        float s0 = sel[0*4 + a], s1 = sel[1*4 + a], s2 = sel[2*4 + a], s3 = sel[3*4 + a];
        const float4* m4 = reinterpret_cast<const float4*>(mat);
        float4 q0 = m4[0], q1 = m4[1], q2 = m4[2], q3 = m4[3];
        v.x = -(s0*q0.x + s1*q1.x + s2*q2.x + s3*q3.x);
        v.y = -(s0*q0.y + s1*q1.y + s2*q2.y + s3*q3.y);
        v.z = -(s0*q0.z + s1*q1.z + s2*q2.z + s3*q3.z);
        v.w = -(s0*q0.w + s1*q1.w + s2*q2.w + s3*q3.w);
    }

    unsigned run = g_run[s];
    unsigned m = run >> 16;
    unsigned j = run & 0xFFFFu;
    float rowv = (float)(node * 4 + a);
    float cb   = (float)(t * 4u);

    if (m == 1u) {
        // fast path: 4 contiguous entries, float4 stores
        unsigned g = off * 16u + (unsigned)a * cnt * 4u + k * 4u;   // 4-aligned
        float4* rows = reinterpret_cast<float4*>(out);
        float4* cols = reinterpret_cast<float4*>(out + (size_t)NENT);
        float4* vals = reinterpret_cast<float4*>(out + (size_t)2 * NENT);
        rows[g >> 2] = make_float4(rowv, rowv, rowv, rowv);
        cols[g >> 2] = make_float4(cb, cb + 1.0f, cb + 2.0f, cb + 3.0f);
        vals[g >> 2] = v;
    } else {
        // rare path: blocks sharing t interleave by b with stride m
        unsigned k0 = k - j;
        size_t base = (size_t)off * 16u + (size_t)a * cnt * 4u + (size_t)k0 * 4u + j;
        float* rows = out;
        float* cols = out + (size_t)NENT;
        float* vals = out + (size_t)2 * NENT;
        float vb[4] = {v.x, v.y, v.z, v.w};
#pragma unroll
        for (unsigned b = 0; b < 4; b++) {
            size_t pos = base + (size_t)b * m;
            rows[pos] = rowv;
            cols[pos] = cb + (float)b;
            vals[pos] = vb[b];
        }
    }
}

extern "C" void kernel_launch(void* const* d_in, const int* in_sizes, int n_in,
                              void* d_out, int out_size) {
    const float* maps = (const float*)d_in[0];
    const int*   ei   = (const int*)d_in[1];
    float*       out  = (float*)d_out;

    k_zero      <<<(NN*16 + 255)/256, 256>>>();
    k_diag_count<<<(TWO_E + 255)/256, 256>>>(maps, ei);
    k_scan1     <<<NSB, SCAN_B>>>();
    k_scan2     <<<1, 1>>>();
    k_scan3     <<<(NN + 255)/256, 256>>>();
    k_fill      <<<(NE + 255)/256, 256>>>(ei);
    k_sort      <<<(NN + 127)/128, 128>>>();
    {
        unsigned total = (unsigned)NBLK * 4u;
        k_emit  <<<(total + 255)/256, 256>>>(maps, out);
    }
    (void)in_sizes; (void)n_in; (void)out_size;
}

// round 5
// speedup vs baseline: 1.4219x; 1.4219x over previous
#include <cuda_runtime.h>

// Problem constants (fixed by setup_inputs)
#define TWO_E   1600000
#define NE      800000
#define NN      50000
#define NBLK    (NN + 2*NE)          // 1,650,000 blocks total
#define NENT    (NBLK*16)            // 26,400,000 COO entries
#define SCAN_B  1024
#define NSB     ((NN + SCAN_B - 1)/SCAN_B)   // 49
#define MAXL    128                  // per-node capacity (Poisson(32): never exceeded)

// Key layout (u64):  node<<44 | t<<22 | cat<<20 | e
//   node: 16 bits (<= 50000)   t: 17 bits   cat: 2 bits   e: 20 bits (< 800000)
// Within a node segment, node bits are constant, so ordering == (t, cat, e).

// Scratch (static device globals; no allocation)
__device__ float                  g_diag[NN*16];     // maps_diag accumulator
__device__ unsigned int           g_cnt[NN];         // edge-blocks per node
__device__ unsigned int           g_off[NN+1];       // exclusive scan of (cnt+1)
__device__ unsigned int           g_cur[NN];         // fill cursors
__device__ unsigned long long     g_key[NBLK];       // packed keys
__device__ unsigned int           g_run[NBLK];       // (run_len<<16)|idx_in_run
__device__ unsigned int           g_partial[NSB];    // scan partials

__global__ void k_zero() {
    int i = blockIdx.x * blockDim.x + threadIdx.x;
    if (i < NN*16) g_diag[i] = 0.0f;
    if (i < NN)    g_cnt[i]  = 0u;
}

// Per-edge M^T M scatter-add into g_diag (all 2E rows of edge_index[0]),
// plus degree counting for the first E edges.
__global__ void k_diag_count(const float* __restrict__ maps,
                             const int*   __restrict__ ei) {
    int j = blockIdx.x * blockDim.x + threadIdx.x;
    if (j >= TWO_E) return;
    const float4* M = reinterpret_cast<const float4*>(maps + (size_t)j * 16);
    float4 r0 = M[0], r1 = M[1], r2 = M[2], r3 = M[3];
    float m[4][4] = {
        {r0.x, r0.y, r0.z, r0.w},
        {r1.x, r1.y, r1.z, r1.w},
        {r2.x, r2.y, r2.z, r2.w},
        {r3.x, r3.y, r3.z, r3.w}
    };
    int node = ei[j];                       // edge_index[0][j]
    float* dst = g_diag + (size_t)node * 16;
#pragma unroll
    for (int a = 0; a < 4; a++) {
#pragma unroll
        for (int b = 0; b < 4; b++) {
            float c = m[0][a]*m[0][b] + m[1][a]*m[1][b]
                    + m[2][a]*m[2][b] + m[3][a]*m[3][b];
            atomicAdd(dst + a*4 + b, c);
        }
    }
    if (j < NE) {
        atomicAdd(&g_cnt[node], 1u);               // row[e]  (cat1 block)
        atomicAdd(&g_cnt[ei[TWO_E + j]], 1u);      // col[e]  (cat2 block)
    }
}

// 3-launch exclusive scan over (cnt[i] + 1)
__global__ void k_scan1() {
    __shared__ unsigned sh[SCAN_B];
    unsigned i = blockIdx.x * SCAN_B + threadIdx.x;
    unsigned v = (i < NN) ? (g_cnt[i] + 1u) : 0u;
    sh[threadIdx.x] = v;
    __syncthreads();
    for (int d = 1; d < SCAN_B; d <<= 1) {
        unsigned t = (threadIdx.x >= (unsigned)d) ? sh[threadIdx.x - d] : 0u;
        __syncthreads();
        sh[threadIdx.x] += t;
        __syncthreads();
    }
    if (i < NN) g_off[i] = sh[threadIdx.x] - v;     // exclusive within block
    if (threadIdx.x == SCAN_B - 1) g_partial[blockIdx.x] = sh[SCAN_B - 1];
}

__global__ void k_scan2() {
    unsigned run = 0;
    for (int b = 0; b < NSB; b++) {
        unsigned t = g_partial[b];
        g_partial[b] = run;
        run += t;
    }
    g_off[NN] = run;    // == NBLK
}

// Finish scan; also seed diag block key + cursor per node.
__global__ void k_scan3() {
    unsigned i = blockIdx.x * blockDim.x + threadIdx.x;
    if (i >= NN) return;
    unsigned o = g_off[i] + g_partial[i >> 10];
    g_off[i] = o;
    g_key[o] = ((unsigned long long)i << 44) | ((unsigned long long)i << 22); // diag: t=node, cat=0, e=0
    g_cur[i] = o + 1u;
}

// Fill edge blocks: cat1 under row[e] targeting col[e]; cat2 under col[e] targeting row[e].
__global__ void k_fill(const int* __restrict__ ei) {
    int e = blockIdx.x * blockDim.x + threadIdx.x;
    if (e >= NE) return;
    unsigned r = (unsigned)ei[e];
    unsigned c = (unsigned)ei[TWO_E + e];
    unsigned s1 = atomicAdd(&g_cur[r], 1u);
    g_key[s1] = ((unsigned long long)r << 44) | ((unsigned long long)c << 22)
              | (1ull << 20) | (unsigned long long)e;
    unsigned s2 = atomicAdd(&g_cur[c], 1u);
    g_key[s2] = ((unsigned long long)c << 44) | ((unsigned long long)r << 22)
              | (2ull << 20) | (unsigned long long)e;
}

// Warp-per-node rank sort. One O(cnt) broadcast loop per key computes:
//   rank = #keys smaller  (keys unique within node)
//   m    = #keys with same target t (run length)
//   j    = #same-t keys smaller (index within run)
// Scatter key+run info to the rank position. cnt^2/32 parallel steps, no
// local memory, fused run detection.
__global__ void k_sort() {
    unsigned gw = (blockIdx.x * blockDim.x + threadIdx.x) >> 5;
    int lane = threadIdx.x & 31;
    int wloc = (int)(threadIdx.x >> 5);
    __shared__ unsigned long long sh[4][MAXL];
    if (gw >= NN) return;
    unsigned off = g_off[gw];
    int cnt = (int)(g_off[gw + 1] - off);

    if (cnt <= MAXL) {
        unsigned long long* buf = sh[wloc];
        for (int i = lane; i < cnt; i += 32) buf[i] = g_key[off + i];
        __syncwarp();
        for (int i = lane; i < cnt; i += 32) {
            unsigned long long x = buf[i];
            unsigned long long tx = x >> 22;            // node|t (node constant)
            int rank = 0; unsigned m = 0, j = 0;
            for (int q = 0; q < cnt; q++) {
                unsigned long long y = buf[q];
                bool lt = (y < x);
                bool eqt = ((y >> 22) == tx);
                rank += lt;
                m    += eqt;
                j    += (eqt && lt);
            }
            g_key[off + rank] = x;
            g_run[off + rank] = (m << 16) | j;
        }
    } else if (lane == 0) {
        // safety fallback; never triggers for this dataset
        for (int i = 1; i < cnt; i++) {
            unsigned long long x = g_key[off + i];
            int j = i - 1;
            while (j >= 0 && g_key[off + j] > x) { g_key[off + j + 1] = g_key[off + j]; j--; }
            g_key[off + j + 1] = x;
        }
        int i = 0;
        while (i < cnt) {
            unsigned long long t = g_key[off + i] >> 22;
            int j = i + 1;
            while (j < cnt && (g_key[off + j] >> 22) == t) j++;
            unsigned m = (unsigned)(j - i);
            for (int q = i; q < j; q++)
                g_run[off + q] = (m << 16) | (unsigned)(q - i);
            i = j;
        }
    }
}

// Emit: one thread per (block slot, a). Within a (node, a) output row the
// entry order is (t, b, cat, e): blocks with distinct t emit 4 contiguous
// entries; runs of m>1 blocks sharing t emit b-interleaved (stride m).
__global__ void k_emit(const float* __restrict__ maps,
                       float* __restrict__ out) {
    unsigned tid = blockIdx.x * blockDim.x + threadIdx.x;
    if (tid >= (unsigned)NBLK * 4u) return;
    unsigned s = tid >> 2;
    int a = (int)(tid & 3u);

    unsigned long long key = g_key[s];
    unsigned node = (unsigned)(key >> 44);
    unsigned t    = (unsigned)(key >> 22) & 0x3FFFFFu;
    int      cat  = (int)((key >> 20) & 3ull);
    unsigned e    = (unsigned)(key & 0xFFFFFull);

    unsigned off = g_off[node];
    unsigned cnt = g_off[node + 1] - off;
    unsigned k   = s - off;

    float4 v;
    if (cat == 0) {
        v = *reinterpret_cast<const float4*>(g_diag + (size_t)node * 16 + a * 4);
    } else {
        const float* L = maps + (size_t)e * 16;
        const float* R = maps + (size_t)(NE + e) * 16;
        // cat1: v[b] = -sum_r L[r][a] * R[r][b]   (triu[a][b])
        // cat2: v[b] = -sum_r R[r][a] * L[r][b]   (triu[b][a])
        const float* sel = (cat == 1) ? L : R;
        const float* mat = (cat == 1) ? R : L;
        float s0 = sel[0*4 + a], s1 = sel[1*4 + a], s2 = sel[2*4 + a], s3 = sel[3*4 + a];
        const float4* m4 = reinterpret_cast<const float4*>(mat);
        float4 q0 = m4[0], q1 = m4[1], q2 = m4[2], q3 = m4[3];
        v.x = -(s0*q0.x + s1*q1.x + s2*q2.x + s3*q3.x);
        v.y = -(s0*q0.y + s1*q1.y + s2*q2.y + s3*q3.y);
        v.z = -(s0*q0.z + s1*q1.z + s2*q2.z + s3*q3.z);
        v.w = -(s0*q0.w + s1*q1.w + s2*q2.w + s3*q3.w);
    }

    unsigned run = g_run[s];
    unsigned m = run >> 16;
    unsigned j = run & 0xFFFFu;
    float rowv = (float)(node * 4 + a);
    float cb   = (float)(t * 4u);

    if (m == 1u) {
        // fast path: 4 contiguous entries, float4 stores
        unsigned g = off * 16u + (unsigned)a * cnt * 4u + k * 4u;   // 4-aligned
        float4* rows = reinterpret_cast<float4*>(out);
        float4* cols = reinterpret_cast<float4*>(out + (size_t)NENT);
        float4* vals = reinterpret_cast<float4*>(out + (size_t)2 * NENT);
        rows[g >> 2] = make_float4(rowv, rowv, rowv, rowv);
        cols[g >> 2] = make_float4(cb, cb + 1.0f, cb + 2.0f, cb + 3.0f);
        vals[g >> 2] = v;
    } else {
        // rare path: blocks sharing t interleave by b with stride m
        unsigned k0 = k - j;
        size_t base = (size_t)off * 16u + (size_t)a * cnt * 4u + (size_t)k0 * 4u + j;
        float* rows = out;
        float* cols = out + (size_t)NENT;
        float* vals = out + (size_t)2 * NENT;
        float vb[4] = {v.x, v.y, v.z, v.w};
#pragma unroll
        for (unsigned b = 0; b < 4; b++) {
            size_t pos = base + (size_t)b * m;
            rows[pos] = rowv;
            cols[pos] = cb + (float)b;
            vals[pos] = vb[b];
        }
    }
}

extern "C" void kernel_launch(void* const* d_in, const int* in_sizes, int n_in,
                              void* d_out, int out_size) {
    const float* maps = (const float*)d_in[0];
    const int*   ei   = (const int*)d_in[1];
    float*       out  = (float*)d_out;

    k_zero      <<<(NN*16 + 255)/256, 256>>>();
    k_diag_count<<<(TWO_E + 255)/256, 256>>>(maps, ei);
    k_scan1     <<<NSB, SCAN_B>>>();
    k_scan2     <<<1, 1>>>();
    k_scan3     <<<(NN + 255)/256, 256>>>();
    k_fill      <<<(NE + 255)/256, 256>>>(ei);
    k_sort      <<<(NN*32 + 127)/128, 128>>>();
    {
        unsigned total = (unsigned)NBLK * 4u;
        k_emit  <<<(total + 255)/256, 256>>>(maps, out);
    }
    (void)in_sizes; (void)n_in; (void)out_size;
}

// round 6
// speedup vs baseline: 1.6509x; 1.1611x over previous
#include <cuda_runtime.h>

// Problem constants (fixed by setup_inputs)
#define TWO_E   1600000
#define NE      800000
#define NN      50000
#define NBLK    (NN + 2*NE)          // 1,650,000 blocks total
#define NENT    (NBLK*16)            // 26,400,000 COO entries
#define SCAN_B  1024
#define NSB     ((NN + SCAN_B - 1)/SCAN_B)   // 49
#define MAXL    128                  // per-node capacity (Poisson(32): never exceeded)

// Key layout (u64):  node<<44 | t<<22 | cat<<20 | e
//   node: 16 bits (<= 50000)   t: 17 bits   cat: 2 bits   e: 20 bits (< 800000)
// Within a node segment, node bits are constant, so ordering == (t, cat, e).

// Scratch (static device globals; no allocation)
__device__ float                  g_diag[NN*16];     // maps_diag accumulator
__device__ unsigned int           g_cnt[NN];         // edge-blocks per node
__device__ unsigned int           g_off[NN+1];       // exclusive scan of (cnt+1)
__device__ unsigned int           g_cur[NN];         // fill cursors
__device__ unsigned long long     g_key[NBLK];       // packed keys
__device__ unsigned int           g_run[NBLK];       // (run_len<<16)|idx_in_run
__device__ unsigned int           g_partial[NSB];    // scan partials

__global__ void k_zero() {
    int i = blockIdx.x * blockDim.x + threadIdx.x;
    if (i < NN*16) g_diag[i] = 0.0f;
    if (i < NN)    g_cnt[i]  = 0u;
}

// Per-edge M^T M scatter-add into g_diag (all 2E rows of edge_index[0]) using
// vectorized L2 reductions (red.global.add.v4.f32: 4 ops/edge instead of 16),
// plus degree counting for the first E edges.
__global__ void k_diag_count(const float* __restrict__ maps,
                             const int*   __restrict__ ei) {
    int j = blockIdx.x * blockDim.x + threadIdx.x;
    if (j >= TWO_E) return;
    const float4* M = reinterpret_cast<const float4*>(maps + (size_t)j * 16);
    float4 r0 = M[0], r1 = M[1], r2 = M[2], r3 = M[3];
    float m[4][4] = {
        {r0.x, r0.y, r0.z, r0.w},
        {r1.x, r1.y, r1.z, r1.w},
        {r2.x, r2.y, r2.z, r2.w},
        {r3.x, r3.y, r3.z, r3.w}
    };
    int node = ei[j];                       // edge_index[0][j]
    float* dst = g_diag + (size_t)node * 16;
#pragma unroll
    for (int a = 0; a < 4; a++) {
        float c0 = m[0][a]*m[0][0] + m[1][a]*m[1][0] + m[2][a]*m[2][0] + m[3][a]*m[3][0];
        float c1 = m[0][a]*m[0][1] + m[1][a]*m[1][1] + m[2][a]*m[2][1] + m[3][a]*m[3][1];
        float c2 = m[0][a]*m[0][2] + m[1][a]*m[1][2] + m[2][a]*m[2][2] + m[3][a]*m[3][2];
        float c3 = m[0][a]*m[0][3] + m[1][a]*m[1][3] + m[2][a]*m[2][3] + m[3][a]*m[3][3];
        asm volatile("red.global.add.v4.f32 [%0], {%1, %2, %3, %4};"
                     :: "l"(dst + a*4), "f"(c0), "f"(c1), "f"(c2), "f"(c3)
                     : "memory");
    }
    if (j < NE) {
        atomicAdd(&g_cnt[node], 1u);               // row[e]  (cat1 block)
        atomicAdd(&g_cnt[ei[TWO_E + j]], 1u);      // col[e]  (cat2 block)
    }
}

// Scan phase 1: per-block exclusive scan over (cnt[i] + 1)
__global__ void k_scan1() {
    __shared__ unsigned sh[SCAN_B];
    unsigned i = blockIdx.x * SCAN_B + threadIdx.x;
    unsigned v = (i < NN) ? (g_cnt[i] + 1u) : 0u;
    sh[threadIdx.x] = v;
    __syncthreads();
    for (int d = 1; d < SCAN_B; d <<= 1) {
        unsigned t = (threadIdx.x >= (unsigned)d) ? sh[threadIdx.x - d] : 0u;
        __syncthreads();
        sh[threadIdx.x] += t;
        __syncthreads();
    }
    if (i < NN) g_off[i] = sh[threadIdx.x] - v;     // exclusive within block
    if (threadIdx.x == SCAN_B - 1) g_partial[blockIdx.x] = sh[SCAN_B - 1];
}

// Fused scan phases 2+3 (single block): serial prefix over 49 partials, then
// block-wide finish: final offsets, diag key seed, fill cursors.
__global__ void k_scan23() {
    if (threadIdx.x == 0) {
        unsigned run = 0;
        for (int b = 0; b < NSB; b++) {
            unsigned t = g_partial[b];
            g_partial[b] = run;
            run += t;
        }
        g_off[NN] = run;    // == NBLK
    }
    __syncthreads();
    for (unsigned i = threadIdx.x; i < NN; i += blockDim.x) {
        unsigned o = g_off[i] + g_partial[i >> 10];
        g_off[i] = o;
        g_key[o] = ((unsigned long long)i << 44) | ((unsigned long long)i << 22); // diag
        g_cur[i] = o + 1u;
    }
}

// Fill edge blocks: cat1 under row[e] targeting col[e]; cat2 under col[e] targeting row[e].
__global__ void k_fill(const int* __restrict__ ei) {
    int e = blockIdx.x * blockDim.x + threadIdx.x;
    if (e >= NE) return;
    unsigned r = (unsigned)ei[e];
    unsigned c = (unsigned)ei[TWO_E + e];
    unsigned s1 = atomicAdd(&g_cur[r], 1u);
    g_key[s1] = ((unsigned long long)r << 44) | ((unsigned long long)c << 22)
              | (1ull << 20) | (unsigned long long)e;
    unsigned s2 = atomicAdd(&g_cur[c], 1u);
    g_key[s2] = ((unsigned long long)c << 44) | ((unsigned long long)r << 22)
              | (2ull << 20) | (unsigned long long)e;
}

// Warp-per-node rank sort. One O(cnt) broadcast loop per key computes:
//   rank = #keys smaller  (keys unique within node)
//   m    = #keys with same target t (run length)
//   j    = #same-t keys smaller (index within run)
// Scatter key+run info to the rank position. cnt^2/32 parallel steps, no
// local memory, fused run detection.
__global__ void k_sort() {
    unsigned gw = (blockIdx.x * blockDim.x + threadIdx.x) >> 5;
    int lane = threadIdx.x & 31;
    int wloc = (int)(threadIdx.x >> 5);
    __shared__ unsigned long long sh[4][MAXL];
    if (gw >= NN) return;
    unsigned off = g_off[gw];
    int cnt = (int)(g_off[gw + 1] - off);

    if (cnt <= MAXL) {
        unsigned long long* buf = sh[wloc];
        for (int i = lane; i < cnt; i += 32) buf[i] = g_key[off + i];
        __syncwarp();
        for (int i = lane; i < cnt; i += 32) {
            unsigned long long x = buf[i];
            unsigned long long tx = x >> 22;            // node|t (node constant)
            int rank = 0; unsigned m = 0, j = 0;
            for (int q = 0; q < cnt; q++) {
                unsigned long long y = buf[q];
                bool lt = (y < x);
                bool eqt = ((y >> 22) == tx);
                rank += lt;
                m    += eqt;
                j    += (eqt && lt);
            }
            g_key[off + rank] = x;
            g_run[off + rank] = (m << 16) | j;
        }
    } else if (lane == 0) {
        // safety fallback; never triggers for this dataset
        for (int i = 1; i < cnt; i++) {
            unsigned long long x = g_key[off + i];
            int j = i - 1;
            while (j >= 0 && g_key[off + j] > x) { g_key[off + j + 1] = g_key[off + j]; j--; }
            g_key[off + j + 1] = x;
        }
        int i = 0;
        while (i < cnt) {
            unsigned long long t = g_key[off + i] >> 22;
            int j = i + 1;
            while (j < cnt && (g_key[off + j] >> 22) == t) j++;
            unsigned m = (unsigned)(j - i);
            for (int q = i; q < j; q++)
                g_run[off + q] = (m << 16) | (unsigned)(q - i);
            i = j;
        }
    }
}

// Emit: one thread per (block slot, a). Within a (node, a) output row the
// entry order is (t, b, cat, e): blocks with distinct t emit 4 contiguous
// entries; runs of m>1 blocks sharing t emit b-interleaved (stride m).
__global__ void k_emit(const float* __restrict__ maps,
                       float* __restrict__ out) {
    unsigned tid = blockIdx.x * blockDim.x + threadIdx.x;
    if (tid >= (unsigned)NBLK * 4u) return;
    unsigned s = tid >> 2;
    int a = (int)(tid & 3u);

    unsigned long long key = g_key[s];
    unsigned node = (unsigned)(key >> 44);
    unsigned t    = (unsigned)(key >> 22) & 0x3FFFFFu;
    int      cat  = (int)((key >> 20) & 3ull);
    unsigned e    = (unsigned)(key & 0xFFFFFull);

    unsigned off = g_off[node];
    unsigned cnt = g_off[node + 1] - off;
    unsigned k   = s - off;

    float4 v;
    if (cat == 0) {
        v = *reinterpret_cast<const float4*>(g_diag + (size_t)node * 16 + a * 4);
    } else {
        const float* L = maps + (size_t)e * 16;
        const float* R = maps + (size_t)(NE + e) * 16;
        // cat1: v[b] = -sum_r L[r][a] * R[r][b]   (triu[a][b])
        // cat2: v[b] = -sum_r R[r][a] * L[r][b]   (triu[b][a])
        const float* sel = (cat == 1) ? L : R;
        const float* mat = (cat == 1) ? R : L;
        float s0 = sel[0*4 + a], s1 = sel[1*4 + a], s2 = sel[2*4 + a], s3 = sel[3*4 + a];
        const float4* m4 = reinterpret_cast<const float4*>(mat);
        float4 q0 = m4[0], q1 = m4[1], q2 = m4[2], q3 = m4[3];
        v.x = -(s0*q0.x + s1*q1.x + s2*q2.x + s3*q3.x);
        v.y = -(s0*q0.y + s1*q1.y + s2*q2.y + s3*q3.y);
        v.z = -(s0*q0.z + s1*q1.z + s2*q2.z + s3*q3.z);
        v.w = -(s0*q0.w + s1*q1.w + s2*q2.w + s3*q3.w);
    }

    unsigned run = g_run[s];
    unsigned m = run >> 16;
    unsigned j = run & 0xFFFFu;
    float rowv = (float)(node * 4 + a);
    float cb   = (float)(t * 4u);

    if (m == 1u) {
        // fast path: 4 contiguous entries, float4 stores
        unsigned g = off * 16u + (unsigned)a * cnt * 4u + k * 4u;   // 4-aligned
        float4* rows = reinterpret_cast<float4*>(out);
        float4* cols = reinterpret_cast<float4*>(out + (size_t)NENT);
        float4* vals = reinterpret_cast<float4*>(out + (size_t)2 * NENT);
        rows[g >> 2] = make_float4(rowv, rowv, rowv, rowv);
        cols[g >> 2] = make_float4(cb, cb + 1.0f, cb + 2.0f, cb + 3.0f);
        vals[g >> 2] = v;
    } else {
        // rare path: blocks sharing t interleave by b with stride m
        unsigned k0 = k - j;
        size_t base = (size_t)off * 16u + (size_t)a * cnt * 4u + (size_t)k0 * 4u + j;
        float* rows = out;
        float* cols = out + (size_t)NENT;
        float* vals = out + (size_t)2 * NENT;
        float vb[4] = {v.x, v.y, v.z, v.w};
#pragma unroll
        for (unsigned b = 0; b < 4; b++) {
            size_t pos = base + (size_t)b * m;
            rows[pos] = rowv;
            cols[pos] = cb + (float)b;
            vals[pos] = vb[b];
        }
    }
}

extern "C" void kernel_launch(void* const* d_in, const int* in_sizes, int n_in,
                              void* d_out, int out_size) {
    const float* maps = (const float*)d_in[0];
    const int*   ei   = (const int*)d_in[1];
    float*       out  = (float*)d_out;

    k_zero      <<<(NN*16 + 255)/256, 256>>>();
    k_diag_count<<<(TWO_E + 255)/256, 256>>>(maps, ei);
    k_scan1     <<<NSB, SCAN_B>>>();
    k_scan23    <<<1, SCAN_B>>>();
    k_fill      <<<(NE + 255)/256, 256>>>(ei);
    k_sort      <<<(NN*32 + 127)/128, 128>>>();
    {
        unsigned total = (unsigned)NBLK * 4u;
        k_emit  <<<(total + 255)/256, 256>>>(maps, out);
    }
    (void)in_sizes; (void)n_in; (void)out_size;
}

// round 7
// speedup vs baseline: 1.9345x; 1.1718x over previous
#include <cuda_runtime.h>

// Problem constants (fixed by setup_inputs)
#define TWO_E   1600000
#define NE      800000
#define NN      50000
#define NBLK    (NN + 2*NE)          // 1,650,000 blocks total
#define NENT    (NBLK*16)            // 26,400,000 COO entries
#define SCAN_B  1024
#define NSB     ((NN + SCAN_B - 1)/SCAN_B)   // 49
#define MAXL    128                  // per-node capacity (Poisson(32): never exceeded)

// Key layout (u64):  node<<44 | t<<22 | cat<<20 | e
//   node: 16 bits (<= 50000)   t: 17 bits   cat: 2 bits   e: 20 bits (< 800000)
// Within a node segment, node bits are constant, so ordering == (t, cat, e).

// Scratch (static device globals; no allocation)
__device__ float                  g_diag[NN*16];     // maps_diag accumulator
__device__ unsigned int           g_cnt[NN];         // edge-blocks per node
__device__ unsigned int           g_off[NN+1];       // exclusive scan of (cnt+1)
__device__ unsigned int           g_cur[NN];         // fill cursors
__device__ unsigned long long     g_key[NBLK];       // packed keys
__device__ unsigned int           g_run[NBLK];       // (run_len<<16)|idx_in_run
__device__ unsigned int           g_partial[NSB];    // scan partials

__global__ void k_zero() {
    int i = blockIdx.x * blockDim.x + threadIdx.x;
    if (i < NN*16) g_diag[i] = 0.0f;
    if (i < NN)    g_cnt[i]  = 0u;
}

// Per-edge M^T M scatter-add into g_diag (all 2E rows of edge_index[0]) using
// vectorized L2 reductions (red.global.add.v4.f32: 4 ops/edge instead of 16),
// plus degree counting for the first E edges.
__global__ void k_diag_count(const float* __restrict__ maps,
                             const int*   __restrict__ ei) {
    int j = blockIdx.x * blockDim.x + threadIdx.x;
    if (j >= TWO_E) return;
    const float4* M = reinterpret_cast<const float4*>(maps + (size_t)j * 16);
    float4 r0 = M[0], r1 = M[1], r2 = M[2], r3 = M[3];
    float m[4][4] = {
        {r0.x, r0.y, r0.z, r0.w},
        {r1.x, r1.y, r1.z, r1.w},
        {r2.x, r2.y, r2.z, r2.w},
        {r3.x, r3.y, r3.z, r3.w}
    };
    int node = ei[j];                       // edge_index[0][j]
    float* dst = g_diag + (size_t)node * 16;
#pragma unroll
    for (int a = 0; a < 4; a++) {
        float c0 = m[0][a]*m[0][0] + m[1][a]*m[1][0] + m[2][a]*m[2][0] + m[3][a]*m[3][0];
        float c1 = m[0][a]*m[0][1] + m[1][a]*m[1][1] + m[2][a]*m[2][1] + m[3][a]*m[3][1];
        float c2 = m[0][a]*m[0][2] + m[1][a]*m[1][2] + m[2][a]*m[2][2] + m[3][a]*m[3][2];
        float c3 = m[0][a]*m[0][3] + m[1][a]*m[1][3] + m[2][a]*m[2][3] + m[3][a]*m[3][3];
        asm volatile("red.global.add.v4.f32 [%0], {%1, %2, %3, %4};"
                     :: "l"(dst + a*4), "f"(c0), "f"(c1), "f"(c2), "f"(c3)
                     : "memory");
    }
    if (j < NE) {
        atomicAdd(&g_cnt[node], 1u);               // row[e]  (cat1 block)
        atomicAdd(&g_cnt[ei[TWO_E + j]], 1u);      // col[e]  (cat2 block)
    }
}

// Scan phase 1: per-block exclusive scan over (cnt[i] + 1)
__global__ void k_scan1() {
    __shared__ unsigned sh[SCAN_B];
    unsigned i = blockIdx.x * SCAN_B + threadIdx.x;
    unsigned v = (i < NN) ? (g_cnt[i] + 1u) : 0u;
    sh[threadIdx.x] = v;
    __syncthreads();
    for (int d = 1; d < SCAN_B; d <<= 1) {
        unsigned t = (threadIdx.x >= (unsigned)d) ? sh[threadIdx.x - d] : 0u;
        __syncthreads();
        sh[threadIdx.x] += t;
        __syncthreads();
    }
    if (i < NN) g_off[i] = sh[threadIdx.x] - v;     // exclusive within block
    if (threadIdx.x == SCAN_B - 1) g_partial[blockIdx.x] = sh[SCAN_B - 1];
}

// Scan phase 2: tiny serial prefix over 49 block partials (1 thread, ~4us).
__global__ void k_scan2() {
    unsigned run = 0;
    for (int b = 0; b < NSB; b++) {
        unsigned t = g_partial[b];
        g_partial[b] = run;
        run += t;
    }
    g_off[NN] = run;    // == NBLK
}

// Scan phase 3 (full grid): final offsets, diag key seed, fill cursors.
__global__ void k_scan3() {
    unsigned i = blockIdx.x * blockDim.x + threadIdx.x;
    if (i >= NN) return;
    unsigned o = g_off[i] + g_partial[i >> 10];
    g_off[i] = o;
    g_key[o] = ((unsigned long long)i << 44) | ((unsigned long long)i << 22); // diag
    g_cur[i] = o + 1u;
}

// Fill edge blocks: cat1 under row[e] targeting col[e]; cat2 under col[e] targeting row[e].
__global__ void k_fill(const int* __restrict__ ei) {
    int e = blockIdx.x * blockDim.x + threadIdx.x;
    if (e >= NE) return;
    unsigned r = (unsigned)ei[e];
    unsigned c = (unsigned)ei[TWO_E + e];
    unsigned s1 = atomicAdd(&g_cur[r], 1u);
    g_key[s1] = ((unsigned long long)r << 44) | ((unsigned long long)c << 22)
              | (1ull << 20) | (unsigned long long)e;
    unsigned s2 = atomicAdd(&g_cur[c], 1u);
    g_key[s2] = ((unsigned long long)c << 44) | ((unsigned long long)r << 22)
              | (2ull << 20) | (unsigned long long)e;
}

// Warp-per-node rank sort. One O(cnt) broadcast loop per key computes:
//   rank = #keys smaller  (keys unique within node)
//   m    = #keys with same target t (run length)
//   j    = #same-t keys smaller (index within run)
// Scatter key+run info to the rank position. cnt^2/32 parallel steps, no
// local memory, fused run detection.
__global__ void k_sort() {
    unsigned gw = (blockIdx.x * blockDim.x + threadIdx.x) >> 5;
    int lane = threadIdx.x & 31;
    int wloc = (int)(threadIdx.x >> 5);
    __shared__ unsigned long long sh[4][MAXL];
    if (gw >= NN) return;
    unsigned off = g_off[gw];
    int cnt = (int)(g_off[gw + 1] - off);

    if (cnt <= MAXL) {
        unsigned long long* buf = sh[wloc];
        for (int i = lane; i < cnt; i += 32) buf[i] = g_key[off + i];
        __syncwarp();
        for (int i = lane; i < cnt; i += 32) {
            unsigned long long x = buf[i];
            unsigned long long tx = x >> 22;            // node|t (node constant)
            int rank = 0; unsigned m = 0, j = 0;
            for (int q = 0; q < cnt; q++) {
                unsigned long long y = buf[q];
                bool lt = (y < x);
                bool eqt = ((y >> 22) == tx);
                rank += lt;
                m    += eqt;
                j    += (eqt && lt);
            }
            g_key[off + rank] = x;
            g_run[off + rank] = (m << 16) | j;
        }
    } else if (lane == 0) {
        // safety fallback; never triggers for this dataset
        for (int i = 1; i < cnt; i++) {
            unsigned long long x = g_key[off + i];
            int j = i - 1;
            while (j >= 0 && g_key[off + j] > x) { g_key[off + j + 1] = g_key[off + j]; j--; }
            g_key[off + j + 1] = x;
        }
        int i = 0;
        while (i < cnt) {
            unsigned long long t = g_key[off + i] >> 22;
            int j = i + 1;
            while (j < cnt && (g_key[off + j] >> 22) == t) j++;
            unsigned m = (unsigned)(j - i);
            for (int q = i; q < j; q++)
                g_run[off + q] = (m << 16) | (unsigned)(q - i);
            i = j;
        }
    }
}

// Emit: one thread per (block slot, a). Within a (node, a) output row the
// entry order is (t, b, cat, e): blocks with distinct t emit 4 contiguous
// entries; runs of m>1 blocks sharing t emit b-interleaved (stride m).
__global__ void k_emit(const float* __restrict__ maps,
                       float* __restrict__ out) {
    unsigned tid = blockIdx.x * blockDim.x + threadIdx.x;
    if (tid >= (unsigned)NBLK * 4u) return;
    unsigned s = tid >> 2;
    int a = (int)(tid & 3u);

    unsigned long long key = g_key[s];
    unsigned node = (unsigned)(key >> 44);
    unsigned t    = (unsigned)(key >> 22) & 0x3FFFFFu;
    int      cat  = (int)((key >> 20) & 3ull);
    unsigned e    = (unsigned)(key & 0xFFFFFull);

    unsigned off = g_off[node];
    unsigned cnt = g_off[node + 1] - off;
    unsigned k   = s - off;

    float4 v;
    if (cat == 0) {
        v = *reinterpret_cast<const float4*>(g_diag + (size_t)node * 16 + a * 4);
    } else {
        const float* L = maps + (size_t)e * 16;
        const float* R = maps + (size_t)(NE + e) * 16;
        // cat1: v[b] = -sum_r L[r][a] * R[r][b]   (triu[a][b])
        // cat2: v[b] = -sum_r R[r][a] * L[r][b]   (triu[b][a])
        const float* sel = (cat == 1) ? L : R;
        const float* mat = (cat == 1) ? R : L;
        float s0 = sel[0*4 + a], s1 = sel[1*4 + a], s2 = sel[2*4 + a], s3 = sel[3*4 + a];
        const float4* m4 = reinterpret_cast<const float4*>(mat);
        float4 q0 = m4[0], q1 = m4[1], q2 = m4[2], q3 = m4[3];
        v.x = -(s0*q0.x + s1*q1.x + s2*q2.x + s3*q3.x);
        v.y = -(s0*q0.y + s1*q1.y + s2*q2.y + s3*q3.y);
        v.z = -(s0*q0.z + s1*q1.z + s2*q2.z + s3*q3.z);
        v.w = -(s0*q0.w + s1*q1.w + s2*q2.w + s3*q3.w);
    }

    unsigned run = g_run[s];
    unsigned m = run >> 16;
    unsigned j = run & 0xFFFFu;
    float rowv = (float)(node * 4 + a);
    float cb   = (float)(t * 4u);

    if (m == 1u) {
        // fast path: 4 contiguous entries, float4 stores
        unsigned g = off * 16u + (unsigned)a * cnt * 4u + k * 4u;   // 4-aligned
        float4* rows = reinterpret_cast<float4*>(out);
        float4* cols = reinterpret_cast<float4*>(out + (size_t)NENT);
        float4* vals = reinterpret_cast<float4*>(out + (size_t)2 * NENT);
        rows[g >> 2] = make_float4(rowv, rowv, rowv, rowv);
        cols[g >> 2] = make_float4(cb, cb + 1.0f, cb + 2.0f, cb + 3.0f);
        vals[g >> 2] = v;
    } else {
        // rare path: blocks sharing t interleave by b with stride m
        unsigned k0 = k - j;
        size_t base = (size_t)off * 16u + (size_t)a * cnt * 4u + (size_t)k0 * 4u + j;
        float* rows = out;
        float* cols = out + (size_t)NENT;
        float* vals = out + (size_t)2 * NENT;
        float vb[4] = {v.x, v.y, v.z, v.w};
#pragma unroll
        for (unsigned b = 0; b < 4; b++) {
            size_t pos = base + (size_t)b * m;
            rows[pos] = rowv;
            cols[pos] = cb + (float)b;
            vals[pos] = vb[b];
        }
    }
}

extern "C" void kernel_launch(void* const* d_in, const int* in_sizes, int n_in,
                              void* d_out, int out_size) {
    const float* maps = (const float*)d_in[0];
    const int*   ei   = (const int*)d_in[1];
    float*       out  = (float*)d_out;

    k_zero      <<<(NN*16 + 255)/256, 256>>>();
    k_diag_count<<<(TWO_E + 255)/256, 256>>>(maps, ei);
    k_scan1     <<<NSB, SCAN_B>>>();
    k_scan2     <<<1, 1>>>();
    k_scan3     <<<(NN + 255)/256, 256>>>();
    k_fill      <<<(NE + 255)/256, 256>>>(ei);
    k_sort      <<<(NN*32 + 127)/128, 128>>>();
    {
        unsigned total = (unsigned)NBLK * 4u;
        k_emit  <<<(total + 255)/256, 256>>>(maps, out);
    }
    (void)in_sizes; (void)n_in; (void)out_size;
}

// round 8
// speedup vs baseline: 1.9658x; 1.0161x over previous
#include <cuda_runtime.h>

// Problem constants (fixed by setup_inputs)
#define TWO_E   1600000
#define NE      800000
#define NN      50000
#define NBLK    (NN + 2*NE)          // 1,650,000 blocks total
#define NENT    (NBLK*16)            // 26,400,000 COO entries
#define SCAN_B  1024
#define NSB     ((NN + SCAN_B - 1)/SCAN_B)   // 49
#define MAXL    128                  // per-node capacity (Poisson(32): never exceeded)

// Key layout (u64):  node<<44 | t<<22 | cat<<20 | e
//   node: 16 bits (<= 50000)   t: 17 bits   cat: 2 bits   e: 20 bits (< 800000)
// Within a node segment, node bits are constant, so ordering == (t, cat, e).

// g_diag stores the symmetric M^T M accumulation as a packed upper triangle,
// 12 floats per node: [c00,c01,c02,c03, c11,c12,c13,c22, c23,c33, pad,pad]
// tri index for a<=b:  a*4 + b - a*(a+1)/2

// Scratch (static device globals; no allocation)
__device__ float                  g_diag[NN*12];     // packed symmetric diag accum
__device__ unsigned int           g_cnt[NN];         // edge-blocks per node
__device__ unsigned int           g_off[NN+1];       // exclusive scan of (cnt+1)
__device__ unsigned int           g_cur[NN];         // fill cursors
__device__ unsigned long long     g_key[NBLK];       // packed keys
__device__ unsigned int           g_run[NBLK];       // (run_len<<16)|idx_in_run
__device__ unsigned int           g_partial[NSB];    // per-block sums (raw)

__global__ void k_zero() {
    int i = blockIdx.x * blockDim.x + threadIdx.x;
    if (i < NN*12) g_diag[i] = 0.0f;
    if (i < NN)    g_cnt[i]  = 0u;
}

// Per-edge M^T M scatter-add into packed triangle using 3 vector reductions
// (v4+v4+v2) per edge, plus degree counting for the first E edges.
__global__ void k_diag_count(const float* __restrict__ maps,
                             const int*   __restrict__ ei) {
    int j = blockIdx.x * blockDim.x + threadIdx.x;
    if (j >= TWO_E) return;
    const float4* M = reinterpret_cast<const float4*>(maps + (size_t)j * 16);
    float4 r0 = M[0], r1 = M[1], r2 = M[2], r3 = M[3];
    float m[4][4] = {
        {r0.x, r0.y, r0.z, r0.w},
        {r1.x, r1.y, r1.z, r1.w},
        {r2.x, r2.y, r2.z, r2.w},
        {r3.x, r3.y, r3.z, r3.w}
    };
    int node = ei[j];                       // edge_index[0][j]
    float* tri = g_diag + (size_t)node * 12;

    // 10 unique dot products c[a][b] = sum_r m[r][a]*m[r][b], a<=b
    float c00 = m[0][0]*m[0][0] + m[1][0]*m[1][0] + m[2][0]*m[2][0] + m[3][0]*m[3][0];
    float c01 = m[0][0]*m[0][1] + m[1][0]*m[1][1] + m[2][0]*m[2][1] + m[3][0]*m[3][1];
    float c02 = m[0][0]*m[0][2] + m[1][0]*m[1][2] + m[2][0]*m[2][2] + m[3][0]*m[3][2];
    float c03 = m[0][0]*m[0][3] + m[1][0]*m[1][3] + m[2][0]*m[2][3] + m[3][0]*m[3][3];
    float c11 = m[0][1]*m[0][1] + m[1][1]*m[1][1] + m[2][1]*m[2][1] + m[3][1]*m[3][1];
    float c12 = m[0][1]*m[0][2] + m[1][1]*m[1][2] + m[2][1]*m[2][2] + m[3][1]*m[3][2];
    float c13 = m[0][1]*m[0][3] + m[1][1]*m[1][3] + m[2][1]*m[2][3] + m[3][1]*m[3][3];
    float c22 = m[0][2]*m[0][2] + m[1][2]*m[1][2] + m[2][2]*m[2][2] + m[3][2]*m[3][2];
    float c23 = m[0][2]*m[0][3] + m[1][2]*m[1][3] + m[2][2]*m[2][3] + m[3][2]*m[3][3];
    float c33 = m[0][3]*m[0][3] + m[1][3]*m[1][3] + m[2][3]*m[2][3] + m[3][3]*m[3][3];

    asm volatile("red.global.add.v4.f32 [%0], {%1, %2, %3, %4};"
                 :: "l"(tri + 0), "f"(c00), "f"(c01), "f"(c02), "f"(c03) : "memory");
    asm volatile("red.global.add.v4.f32 [%0], {%1, %2, %3, %4};"
                 :: "l"(tri + 4), "f"(c11), "f"(c12), "f"(c13), "f"(c22) : "memory");
    asm volatile("red.global.add.v2.f32 [%0], {%1, %2};"
                 :: "l"(tri + 8), "f"(c23), "f"(c33) : "memory");

    if (j < NE) {
        atomicAdd(&g_cnt[node], 1u);               // row[e]  (cat1 block)
        atomicAdd(&g_cnt[ei[TWO_E + j]], 1u);      // col[e]  (cat2 block)
    }
}

// Scan phase 1: per-block exclusive scan over (cnt[i] + 1); raw block sums -> g_partial
__global__ void k_scan1() {
    __shared__ unsigned sh[SCAN_B];
    unsigned i = blockIdx.x * SCAN_B + threadIdx.x;
    unsigned v = (i < NN) ? (g_cnt[i] + 1u) : 0u;
    sh[threadIdx.x] = v;
    __syncthreads();
    for (int d = 1; d < SCAN_B; d <<= 1) {
        unsigned t = (threadIdx.x >= (unsigned)d) ? sh[threadIdx.x - d] : 0u;
        __syncthreads();
        sh[threadIdx.x] += t;
        __syncthreads();
    }
    if (i < NN) g_off[i] = sh[threadIdx.x] - v;     // exclusive within block
    if (threadIdx.x == SCAN_B - 1) g_partial[blockIdx.x] = sh[SCAN_B - 1];
}

// Scan phase 3 (full grid): each thread sums the raw partials of preceding
// blocks inline (<=48 L1-broadcast loads) — no separate scan2 launch. Also
// seeds diag key + fill cursor; last thread writes the grand total.
__global__ void k_scan3() {
    unsigned i = blockIdx.x * blockDim.x + threadIdx.x;
    if (i >= NN) return;
    unsigned nb = i >> 10;
    unsigned add = 0;
    for (unsigned b = 0; b < nb; b++) add += g_partial[b];
    unsigned o = g_off[i] + add;
    g_off[i] = o;
    g_key[o] = ((unsigned long long)i << 44) | ((unsigned long long)i << 22); // diag
    g_cur[i] = o + 1u;
    if (i == NN - 1) g_off[NN] = o + g_cnt[i] + 1u;   // == NBLK
}

// Fill edge blocks: cat1 under row[e] targeting col[e]; cat2 under col[e] targeting row[e].
__global__ void k_fill(const int* __restrict__ ei) {
    int e = blockIdx.x * blockDim.x + threadIdx.x;
    if (e >= NE) return;
    unsigned r = (unsigned)ei[e];
    unsigned c = (unsigned)ei[TWO_E + e];
    unsigned s1 = atomicAdd(&g_cur[r], 1u);
    g_key[s1] = ((unsigned long long)r << 44) | ((unsigned long long)c << 22)
              | (1ull << 20) | (unsigned long long)e;
    unsigned s2 = atomicAdd(&g_cur[c], 1u);
    g_key[s2] = ((unsigned long long)c << 44) | ((unsigned long long)r << 22)
              | (2ull << 20) | (unsigned long long)e;
}

// Warp-per-node rank sort. One O(cnt) broadcast loop per key computes:
//   rank = #keys smaller  (keys unique within node)
//   m    = #keys with same target t (run length)
//   j    = #same-t keys smaller (index within run)
// Scatter key+run info to the rank position. cnt^2/32 parallel steps, no
// local memory, fused run detection.
__global__ void k_sort() {
    unsigned gw = (blockIdx.x * blockDim.x + threadIdx.x) >> 5;
    int lane = threadIdx.x & 31;
    int wloc = (int)(threadIdx.x >> 5);
    __shared__ unsigned long long sh[4][MAXL];
    if (gw >= NN) return;
    unsigned off = g_off[gw];
    int cnt = (int)(g_off[gw + 1] - off);

    if (cnt <= MAXL) {
        unsigned long long* buf = sh[wloc];
        for (int i = lane; i < cnt; i += 32) buf[i] = g_key[off + i];
        __syncwarp();
        for (int i = lane; i < cnt; i += 32) {
            unsigned long long x = buf[i];
            unsigned long long tx = x >> 22;            // node|t (node constant)
            int rank = 0; unsigned m = 0, j = 0;
            for (int q = 0; q < cnt; q++) {
                unsigned long long y = buf[q];
                bool lt = (y < x);
                bool eqt = ((y >> 22) == tx);
                rank += lt;
                m    += eqt;
                j    += (eqt && lt);
            }
            g_key[off + rank] = x;
            g_run[off + rank] = (m << 16) | j;
        }
    } else if (lane == 0) {
        // safety fallback; never triggers for this dataset
        for (int i = 1; i < cnt; i++) {
            unsigned long long x = g_key[off + i];
            int j = i - 1;
            while (j >= 0 && g_key[off + j] > x) { g_key[off + j + 1] = g_key[off + j]; j--; }
            g_key[off + j + 1] = x;
        }
        int i = 0;
        while (i < cnt) {
            unsigned long long t = g_key[off + i] >> 22;
            int j = i + 1;
            while (j < cnt && (g_key[off + j] >> 22) == t) j++;
            unsigned m = (unsigned)(j - i);
            for (int q = i; q < j; q++)
                g_run[off + q] = (m << 16) | (unsigned)(q - i);
            i = j;
        }
    }
}

// Emit: one thread per (block slot, a). Within a (node, a) output row the
// entry order is (t, b, cat, e): blocks with distinct t emit 4 contiguous
// entries; runs of m>1 blocks sharing t emit b-interleaved (stride m).
__global__ void k_emit(const float* __restrict__ maps,
                       float* __restrict__ out) {
    unsigned tid = blockIdx.x * blockDim.x + threadIdx.x;
    if (tid >= (unsigned)NBLK * 4u) return;
    unsigned s = tid >> 2;
    int a = (int)(tid & 3u);

    unsigned long long key = g_key[s];
    unsigned node = (unsigned)(key >> 44);
    unsigned t    = (unsigned)(key >> 22) & 0x3FFFFFu;
    int      cat  = (int)((key >> 20) & 3ull);
    unsigned e    = (unsigned)(key & 0xFFFFFull);

    unsigned off = g_off[node];
    unsigned cnt = g_off[node + 1] - off;
    unsigned k   = s - off;

    float4 v;
    if (cat == 0) {
        const float* tri = g_diag + (size_t)node * 12;
        float vb[4];
#pragma unroll
        for (int b = 0; b < 4; b++) {
            int i2 = a < b ? a : b;
            int j2 = a < b ? b : a;
            vb[b] = tri[i2*4 + j2 - ((i2*(i2+1)) >> 1)];
        }
        v = make_float4(vb[0], vb[1], vb[2], vb[3]);
    } else {
        const float* L = maps + (size_t)e * 16;
        const float* R = maps + (size_t)(NE + e) * 16;
        // cat1: v[b] = -sum_r L[r][a] * R[r][b]   (triu[a][b])
        // cat2: v[b] = -sum_r R[r][a] * L[r][b]   (triu[b][a])
        const float* sel = (cat == 1) ? L : R;
        const float* mat = (cat == 1) ? R : L;
        float s0 = sel[0*4 + a], s1 = sel[1*4 + a], s2 = sel[2*4 + a], s3 = sel[3*4 + a];
        const float4* m4 = reinterpret_cast<const float4*>(mat);
        float4 q0 = m4[0], q1 = m4[1], q2 = m4[2], q3 = m4[3];
        v.x = -(s0*q0.x + s1*q1.x + s2*q2.x + s3*q3.x);
        v.y = -(s0*q0.y + s1*q1.y + s2*q2.y + s3*q3.y);
        v.z = -(s0*q0.z + s1*q1.z + s2*q2.z + s3*q3.z);
        v.w = -(s0*q0.w + s1*q1.w + s2*q2.w + s3*q3.w);
    }

    unsigned run = g_run[s];
    unsigned m = run >> 16;
    unsigned j = run & 0xFFFFu;
    float rowv = (float)(node * 4 + a);
    float cb   = (float)(t * 4u);

    if (m == 1u) {
        // fast path: 4 contiguous entries, float4 stores
        unsigned g = off * 16u + (unsigned)a * cnt * 4u + k * 4u;   // 4-aligned
        float4* rows = reinterpret_cast<float4*>(out);
        float4* cols = reinterpret_cast<float4*>(out + (size_t)NENT);
        float4* vals = reinterpret_cast<float4*>(out + (size_t)2 * NENT);
        rows[g >> 2] = make_float4(rowv, rowv, rowv, rowv);
        cols[g >> 2] = make_float4(cb, cb + 1.0f, cb + 2.0f, cb + 3.0f);
        vals[g >> 2] = v;
    } else {
        // rare path: blocks sharing t interleave by b with stride m
        unsigned k0 = k - j;
        size_t base = (size_t)off * 16u + (size_t)a * cnt * 4u + (size_t)k0 * 4u + j;
        float* rows = out;
        float* cols = out + (size_t)NENT;
        float* vals = out + (size_t)2 * NENT;
        float vb[4] = {v.x, v.y, v.z, v.w};
#pragma unroll
        for (unsigned b = 0; b < 4; b++) {
            size_t pos = base + (size_t)b * m;
            rows[pos] = rowv;
            cols[pos] = cb + (float)b;
            vals[pos] = vb[b];
        }
    }
}

extern "C" void kernel_launch(void* const* d_in, const int* in_sizes, int n_in,
                              void* d_out, int out_size) {
    const float* maps = (const float*)d_in[0];
    const int*   ei   = (const int*)d_in[1];
    float*       out  = (float*)d_out;

    k_zero      <<<(NN*12 + 255)/256, 256>>>();
    k_diag_count<<<(TWO_E + 255)/256, 256>>>(maps, ei);
    k_scan1     <<<NSB, SCAN_B>>>();
    k_scan3     <<<(NN + 255)/256, 256>>>();
    k_fill      <<<(NE + 255)/256, 256>>>(ei);
    k_sort      <<<(NN*32 + 127)/128, 128>>>();
    {
        unsigned total = (unsigned)NBLK * 4u;
        k_emit  <<<(total + 255)/256, 256>>>(maps, out);
    }
    (void)in_sizes; (void)n_in; (void)out_size;
}